// round 11
// baseline (speedup 1.0000x reference)
#include <cuda_runtime.h>

#define N_REF   50000
#define Q_NUM   4096
#define TN      339                 // refs per smem tile
#define NTILES  148                 // 339*148 = 50172 >= 50000
#define BLOCK   128
#define QPT     8                   // queries per thread (4 f32x2 pairs)
#define NPAIR   (QPT / 2)           // 4
#define QTILE   (BLOCK * QPT)       // 1024
#define QTILES  (Q_NUM / QTILE)     // 4 -> 4*148 = 592 blocks = 148 SMs * 4
#define NBLOCKS (QTILES * NTILES)   // 592: EXACTLY one wave at occ 4
#define RBLOCKS 512                 // blocks participating in fused reduce
#define RPARTS  64

typedef unsigned long long u64;
typedef unsigned int u32;

// partials: [plane][ntile][q]  (plane 0=w, 1=lx, 2=ly), ~7.3MB
#define PLANE   ((u32)NTILES * Q_NUM)
__device__ float g_partial[3u * PLANE];
// grid-barrier generation counter (monotonic across graph replays)
__device__ u64 g_arrive = 0ull;

// ---------------- f32x2 helpers (Blackwell packed fp32) ----------------
__device__ __forceinline__ u64 fma2(u64 a, u64 b, u64 c) {
    u64 d;
    asm("fma.rn.f32x2 %0, %1, %2, %3;" : "=l"(d) : "l"(a), "l"(b), "l"(c));
    return d;
}
__device__ __forceinline__ u64 add2(u64 a, u64 b) {
    u64 d;
    asm("add.rn.f32x2 %0, %1, %2;" : "=l"(d) : "l"(a), "l"(b));
    return d;
}
__device__ __forceinline__ u64 pack2(float lo, float hi) {
    u64 d;
    asm("mov.b64 %0, {%1, %2};" : "=l"(d) : "f"(lo), "f"(hi));
    return d;
}
__device__ __forceinline__ void unpack2(u64 v, float& lo, float& hi) {
    asm("mov.b64 {%0, %1}, %2;" : "=f"(lo), "=f"(hi) : "l"(v));
}
// raw MUFU.EX2 — exp2 with ~2^-22 rel err, FTZ (ex2(-1e30) -> +0)
__device__ __forceinline__ float ex2(float x) {
    float y;
    asm("ex2.approx.ftz.f32 %0, %1;" : "=f"(y) : "f"(x));
    return y;
}

// ---------------- fused kernel: pack + partial sums + grid-sync reduce ----
// smem per ref (16 floats / 64B):
// {r0,r0,r1,r1,r2,r2,r3,r3,r4,r4,rbar,rbar,l0,l0,l1,l1}, rbar = -k*|r|^2,
// k = log2(e)/(2 sigma^2). w = exp2(rbar + sum_d xs_d*r_d), xs_d = x_d*2k;
// the per-query factor exp2(-k*|x|^2) cancels in the normalization.
// Main loop = R8/R10 best-measured shape (breadth-first chains, EX2 consumed
// one iter late, register double-buffer). Then: one-wave grid barrier
// (592 blocks all co-resident at occ 4) and an in-kernel L2-hot reduction.
__global__ __launch_bounds__(BLOCK, 4)
void sknn_main_kernel(const float* __restrict__ rss,
                      const float* __restrict__ Radio,
                      const float* __restrict__ Loc,
                      const float* __restrict__ sigma,
                      float* __restrict__ out) {
    __shared__ u64 sh[TN * 8];  // 21.7 KB (reused as reduce scratch)
    __shared__ u64 s_target;

    const u32 qtile = blockIdx.x;   // 0..3
    const u32 ntile = blockIdx.y;   // 0..147
    const u32 t     = threadIdx.x;

    const float s  = sigma[0];
    const float k  = 0.5f * 1.4426950408889634f / (s * s);
    const float k2 = 2.0f * k;

    // ---- load 8 queries per thread FIRST (gmem latency overlaps pack) ----
    const u32 q0 = qtile * QTILE + t;
    float qa[NPAIR][5], qb[NPAIR][5];
#pragma unroll
    for (int p = 0; p < NPAIR; p++) {
#pragma unroll
        for (int d = 0; d < 5; d++) {
            qa[p][d] = rss[(q0 + (2 * p + 0) * BLOCK) * 5 + d];
            qb[p][d] = rss[(q0 + (2 * p + 1) * BLOCK) * 5 + d];
        }
    }

    // ---- pack this block's ref tile directly into smem ----
    for (u32 i = t; i < TN; i += BLOCK) {
        const u32 n = ntile * TN + i;
        float o[16];
        if (n < N_REF) {
            float r2 = 0.0f;
#pragma unroll
            for (int d = 0; d < 5; d++) {
                float r = Radio[n * 5 + d];
                o[2 * d] = r;
                o[2 * d + 1] = r;
                r2 = fmaf(r, r, r2);
            }
            float rbar = -k * r2;
            o[10] = rbar; o[11] = rbar;
            float l0 = Loc[n * 2 + 0], l1 = Loc[n * 2 + 1];
            o[12] = l0; o[13] = l0;
            o[14] = l1; o[15] = l1;
        } else {
#pragma unroll
            for (int j = 0; j < 16; j++) o[j] = 0.0f;
            o[10] = -1e30f; o[11] = -1e30f;   // ex2 -> +0: contributes nothing
        }
        float4* dst = reinterpret_cast<float4*>(sh + i * 8);
        const float4* src = reinterpret_cast<const float4*>(o);
        dst[0] = src[0]; dst[1] = src[1]; dst[2] = src[2]; dst[3] = src[3];
    }

    u64 xs[NPAIR][5];
#pragma unroll
    for (int p = 0; p < NPAIR; p++)
#pragma unroll
        for (int d = 0; d < 5; d++)
            xs[p][d] = pack2(qa[p][d] * k2, qb[p][d] * k2);
    __syncthreads();

    u64 wsum[NPAIR], lx[NPAIR], ly[NPAIR];
    u64 evp[NPAIR];                   // pipelined ev from previous iter
    u64 lp0 = 0ull, lp1 = 0ull;       // previous iter's loc values
#pragma unroll
    for (int p = 0; p < NPAIR; p++) {
        wsum[p] = 0ull; lx[p] = 0ull; ly[p] = 0ull; evp[p] = 0ull;
    }

    // register double-buffer: preload ref 0
    const ulonglong2* eptr = reinterpret_cast<const ulonglong2*>(sh);
    ulonglong2 v0 = eptr[0], v1 = eptr[1], v2 = eptr[2], v3 = eptr[3];

#pragma unroll 1
    for (u32 i = 0; i < TN; i++) {
        const u64 r0 = v0.x, r1 = v0.y, r2 = v1.x, r3 = v1.y;
        const u64 r4 = v2.x, rb = v2.y, l0 = v3.x, l1 = v3.y;

        // prefetch next ref (overlaps the whole body below)
        if (i + 1 < TN) {
            const ulonglong2* nx = eptr + (i + 1) * 4;
            v0 = nx[0]; v1 = nx[1]; v2 = nx[2]; v3 = nx[3];
        }

        // breadth-first FMA chains (4 independent)
        u64 acc[NPAIR];
#pragma unroll
        for (int p = 0; p < NPAIR; p++) acc[p] = fma2(xs[p][0], r0, rb);
#pragma unroll
        for (int p = 0; p < NPAIR; p++) acc[p] = fma2(xs[p][1], r1, acc[p]);
#pragma unroll
        for (int p = 0; p < NPAIR; p++) acc[p] = fma2(xs[p][2], r2, acc[p]);

        // accumulate PREVIOUS iteration's ev (MUFU results long ready)
#pragma unroll
        for (int p = 0; p < NPAIR; p++) {
            wsum[p] = add2(wsum[p], evp[p]);
            lx[p]   = fma2(evp[p], lp0, lx[p]);
            ly[p]   = fma2(evp[p], lp1, ly[p]);
        }

#pragma unroll
        for (int p = 0; p < NPAIR; p++) acc[p] = fma2(xs[p][3], r3, acc[p]);
#pragma unroll
        for (int p = 0; p < NPAIR; p++) acc[p] = fma2(xs[p][4], r4, acc[p]);

        // issue this iteration's EX2s; consumed next iteration
#pragma unroll
        for (int p = 0; p < NPAIR; p++) {
            float alo, ahi;
            unpack2(acc[p], alo, ahi);
            evp[p] = pack2(ex2(alo), ex2(ahi));
        }
        lp0 = l0; lp1 = l1;
    }
    // drain the pipeline
#pragma unroll
    for (int p = 0; p < NPAIR; p++) {
        wsum[p] = add2(wsum[p], evp[p]);
        lx[p]   = fma2(evp[p], lp0, lx[p]);
        ly[p]   = fma2(evp[p], lp1, ly[p]);
    }

    // ---- write partials, layout [plane][ntile][q]: warp-coalesced ----
    const u32 row = ntile * Q_NUM + q0;
#pragma unroll
    for (int p = 0; p < NPAIR; p++) {
        float w0, w1, x0, x1, y0, y1;
        unpack2(wsum[p], w0, w1);
        unpack2(lx[p],   x0, x1);
        unpack2(ly[p],   y0, y1);
        u32 ia = row + (2 * p + 0) * BLOCK;   // consecutive q across warp
        u32 ib = row + (2 * p + 1) * BLOCK;
        g_partial[0u * PLANE + ia] = w0;
        g_partial[1u * PLANE + ia] = x0;
        g_partial[2u * PLANE + ia] = y0;
        g_partial[0u * PLANE + ib] = w1;
        g_partial[1u * PLANE + ib] = x1;
        g_partial[2u * PLANE + ib] = y1;
    }

    // ---- one-wave grid barrier ----
    // All NBLOCKS=592 blocks are co-resident (exactly 4/SM on 148 SMs), so
    // spin-waiting is deadlock-free. Generation counter: monotonic, needs no
    // reset between graph replays (kernel instances are stream-ordered).
    __threadfence();   // publish partials (release)
    if (t == 0) {
        u64 ticket = atomicAdd(&g_arrive, 1ull);
        s_target = (ticket / NBLOCKS + 1ull) * NBLOCKS;
    }
    __syncthreads();
    const u32 bflat = blockIdx.y * QTILES + blockIdx.x;   // 0..591
    if (bflat >= RBLOCKS) return;                          // 80 blocks exit
    if (t == 0) {
        const u64 target = s_target;
        while (*(volatile u64*)&g_arrive < target) __nanosleep(128);
    }
    __syncthreads();
    __threadfence();   // acquire: partials now visible

    // ---- in-kernel reduce: block handles 8 queries (2 float4 groups) ----
    // 64 parts x 2 groups; L2-hot __ldcg float4 reads; fixed-order smem
    // tree -> bitwise deterministic (same structure as the R9/R10 reduce).
    {
        float4* sred = reinterpret_cast<float4*>(sh);   // [3][RPARTS][2]
        const u32 part = t >> 1;            // 0..63
        const u32 g    = t & 1;             // group within block
        const u32 q4   = bflat * 2 + g;     // global float4 index

        float4 w = make_float4(0.f, 0.f, 0.f, 0.f);
        float4 x = w, y = w;
        const float4* p0 = reinterpret_cast<const float4*>(g_partial + 0u * PLANE);
        const float4* p1 = reinterpret_cast<const float4*>(g_partial + 1u * PLANE);
        const float4* p2 = reinterpret_cast<const float4*>(g_partial + 2u * PLANE);
        for (u32 c = part; c < NTILES; c += RPARTS) {
            const u32 idx = c * (Q_NUM / 4) + q4;
            float4 a = __ldcg(p0 + idx), b = __ldcg(p1 + idx), d = __ldcg(p2 + idx);
            w.x += a.x; w.y += a.y; w.z += a.z; w.w += a.w;
            x.x += b.x; x.y += b.y; x.z += b.z; x.w += b.w;
            y.x += d.x; y.y += d.y; y.z += d.z; y.w += d.w;
        }
        sred[(0u * RPARTS + part) * 2 + g] = w;
        sred[(1u * RPARTS + part) * 2 + g] = x;
        sred[(2u * RPARTS + part) * 2 + g] = y;
        __syncthreads();

#pragma unroll
        for (u32 sft = RPARTS / 2; sft >= 1; sft >>= 1) {
            if (part < sft) {
#pragma unroll
                for (u32 pl = 0; pl < 3; pl++) {
                    float4 a = sred[(pl * RPARTS + part) * 2 + g];
                    float4 b = sred[(pl * RPARTS + part + sft) * 2 + g];
                    a.x += b.x; a.y += b.y; a.z += b.z; a.w += b.w;
                    sred[(pl * RPARTS + part) * 2 + g] = a;
                }
            }
            __syncthreads();
        }

        if (part == 0) {
            float4 wt = sred[(0u * RPARTS) * 2 + g];
            float4 xt = sred[(1u * RPARTS) * 2 + g];
            float4 yt = sred[(2u * RPARTS) * 2 + g];
            const u32 qb = q4 * 4;
            out[(qb + 0) * 2 + 0] = xt.x / wt.x;
            out[(qb + 0) * 2 + 1] = yt.x / wt.x;
            out[(qb + 1) * 2 + 0] = xt.y / wt.y;
            out[(qb + 1) * 2 + 1] = yt.y / wt.y;
            out[(qb + 2) * 2 + 0] = xt.z / wt.z;
            out[(qb + 2) * 2 + 1] = yt.z / wt.z;
            out[(qb + 3) * 2 + 0] = xt.w / wt.w;
            out[(qb + 3) * 2 + 1] = yt.w / wt.w;
        }
    }
}

// ---------------- launch -------------------------------------------------
extern "C" void kernel_launch(void* const* d_in, const int* in_sizes, int n_in,
                              void* d_out, int out_size) {
    (void)in_sizes; (void)n_in; (void)out_size;
    const float* rss   = (const float*)d_in[0];  // [4096, 5]
    const float* Radio = (const float*)d_in[1];  // [50000, 5]
    const float* Loc   = (const float*)d_in[2];  // [50000, 2]
    const float* sigma = (const float*)d_in[3];  // [1]
    float* out = (float*)d_out;                  // [4096, 2]

    dim3 grid(QTILES, NTILES);
    sknn_main_kernel<<<grid, BLOCK>>>(rss, Radio, Loc, sigma, out);
}

// round 12
// speedup vs baseline: 1.1466x; 1.1466x over previous
#include <cuda_runtime.h>

#define N_REF   50000
#define Q_NUM   4096
#define TN      339                 // refs per smem tile
#define NTILES  148                 // 339*148 = 50172 >= 50000
#define BLOCK   256
#define QPT     8                   // queries per thread (4 f32x2 pairs)
#define NPAIR   (QPT / 2)           // 4
#define QTILE   (BLOCK * QPT)       // 2048
#define QTILES  (Q_NUM / QTILE)     // 2 -> 2*148 = 296 blocks = 148 SMs * 2

typedef unsigned long long u64;
typedef unsigned int u32;

// partials: [plane][ntile][q]  (plane 0=w, 1=lx, 2=ly), ~7.3MB
#define PLANE   ((u32)NTILES * Q_NUM)
__device__ float g_partial[3u * PLANE];

// ---------------- f32x2 helpers (Blackwell packed fp32) ----------------
__device__ __forceinline__ u64 fma2(u64 a, u64 b, u64 c) {
    u64 d;
    asm("fma.rn.f32x2 %0, %1, %2, %3;" : "=l"(d) : "l"(a), "l"(b), "l"(c));
    return d;
}
__device__ __forceinline__ u64 add2(u64 a, u64 b) {
    u64 d;
    asm("add.rn.f32x2 %0, %1, %2;" : "=l"(d) : "l"(a), "l"(b));
    return d;
}
__device__ __forceinline__ u64 pack2(float lo, float hi) {
    u64 d;
    asm("mov.b64 %0, {%1, %2};" : "=l"(d) : "f"(lo), "f"(hi));
    return d;
}
__device__ __forceinline__ void unpack2(u64 v, float& lo, float& hi) {
    asm("mov.b64 {%0, %1}, %2;" : "=f"(lo), "=f"(hi) : "l"(v));
}
// raw MUFU.EX2 — exp2 with ~2^-22 rel err, FTZ (ex2(-1e30) -> +0)
__device__ __forceinline__ float ex2(float x) {
    float y;
    asm("ex2.approx.ftz.f32 %0, %1;" : "=f"(y) : "f"(x));
    return y;
}

// ---------------- main: fused pack + per-tile partial sums --------------
// smem per ref (16 floats / 64B):
// {r0,r0,r1,r1,r2,r2,r3,r3,r4,r4,rbar,rbar,l0,l0,l1,l1}, rbar = -k*|r|^2,
// k = log2(e)/(2 sigma^2). w = exp2(rbar + sum_d xs_d*r_d), xs_d = x_d*2k;
// the per-query factor exp2(-k*|x|^2) cancels in the normalization.
// Inner loop = R8/R10 best-measured shape (breadth-first chains, EX2
// consumed one iteration late, register double-buffer). BLOCK=256/QTILES=2
// halves the pack redundancy vs R10 with identical per-warp behavior.
__global__ __launch_bounds__(BLOCK, 2)
void sknn_main_kernel(const float* __restrict__ rss,
                      const float* __restrict__ Radio,
                      const float* __restrict__ Loc,
                      const float* __restrict__ sigma) {
    __shared__ u64 sh[TN * 8];  // 21.7 KB

    const u32 qtile = blockIdx.x;   // 0..1
    const u32 ntile = blockIdx.y;   // 0..147
    const u32 t     = threadIdx.x;

    const float s  = sigma[0];
    const float k  = 0.5f * 1.4426950408889634f / (s * s);
    const float k2 = 2.0f * k;

    // ---- pack this block's ref tile directly into smem ----
    for (u32 i = t; i < TN; i += BLOCK) {
        const u32 n = ntile * TN + i;
        float o[16];
        if (n < N_REF) {
            float r2 = 0.0f;
#pragma unroll
            for (int d = 0; d < 5; d++) {
                float r = Radio[n * 5 + d];
                o[2 * d] = r;
                o[2 * d + 1] = r;
                r2 = fmaf(r, r, r2);
            }
            float rbar = -k * r2;
            o[10] = rbar; o[11] = rbar;
            float l0 = Loc[n * 2 + 0], l1 = Loc[n * 2 + 1];
            o[12] = l0; o[13] = l0;
            o[14] = l1; o[15] = l1;
        } else {
#pragma unroll
            for (int j = 0; j < 16; j++) o[j] = 0.0f;
            o[10] = -1e30f; o[11] = -1e30f;   // ex2 -> +0: contributes nothing
        }
        float4* dst = reinterpret_cast<float4*>(sh + i * 8);
        const float4* src = reinterpret_cast<const float4*>(o);
        dst[0] = src[0]; dst[1] = src[1]; dst[2] = src[2]; dst[3] = src[3];
    }

    // ---- 8 queries per thread as 4 f32x2 pairs ----
    // pair p holds queries q0 + (2p)*BLOCK and q0 + (2p+1)*BLOCK
    const u32 q0 = qtile * QTILE + t;
    u64 xs[NPAIR][5];
#pragma unroll
    for (int p = 0; p < NPAIR; p++) {
#pragma unroll
        for (int d = 0; d < 5; d++) {
            float a = rss[(q0 + (2 * p + 0) * BLOCK) * 5 + d] * k2;
            float b = rss[(q0 + (2 * p + 1) * BLOCK) * 5 + d] * k2;
            xs[p][d] = pack2(a, b);
        }
    }
    __syncthreads();

    u64 wsum[NPAIR], lx[NPAIR], ly[NPAIR];
    u64 evp[NPAIR];                   // pipelined ev from previous iter
    u64 lp0 = 0ull, lp1 = 0ull;       // previous iter's loc values
#pragma unroll
    for (int p = 0; p < NPAIR; p++) {
        wsum[p] = 0ull; lx[p] = 0ull; ly[p] = 0ull; evp[p] = 0ull;
    }

    // register double-buffer: preload ref 0
    const ulonglong2* eptr = reinterpret_cast<const ulonglong2*>(sh);
    ulonglong2 v0 = eptr[0], v1 = eptr[1], v2 = eptr[2], v3 = eptr[3];

#pragma unroll 1
    for (u32 i = 0; i < TN; i++) {
        const u64 r0 = v0.x, r1 = v0.y, r2 = v1.x, r3 = v1.y;
        const u64 r4 = v2.x, rb = v2.y, l0 = v3.x, l1 = v3.y;

        // prefetch next ref (overlaps the whole body below)
        if (i + 1 < TN) {
            const ulonglong2* nx = eptr + (i + 1) * 4;
            v0 = nx[0]; v1 = nx[1]; v2 = nx[2]; v3 = nx[3];
        }

        // breadth-first FMA chains (4 independent)
        u64 acc[NPAIR];
#pragma unroll
        for (int p = 0; p < NPAIR; p++) acc[p] = fma2(xs[p][0], r0, rb);
#pragma unroll
        for (int p = 0; p < NPAIR; p++) acc[p] = fma2(xs[p][1], r1, acc[p]);
#pragma unroll
        for (int p = 0; p < NPAIR; p++) acc[p] = fma2(xs[p][2], r2, acc[p]);

        // accumulate PREVIOUS iteration's ev (MUFU results long ready)
#pragma unroll
        for (int p = 0; p < NPAIR; p++) {
            wsum[p] = add2(wsum[p], evp[p]);
            lx[p]   = fma2(evp[p], lp0, lx[p]);
            ly[p]   = fma2(evp[p], lp1, ly[p]);
        }

#pragma unroll
        for (int p = 0; p < NPAIR; p++) acc[p] = fma2(xs[p][3], r3, acc[p]);
#pragma unroll
        for (int p = 0; p < NPAIR; p++) acc[p] = fma2(xs[p][4], r4, acc[p]);

        // issue this iteration's EX2s; consumed next iteration
#pragma unroll
        for (int p = 0; p < NPAIR; p++) {
            float alo, ahi;
            unpack2(acc[p], alo, ahi);
            evp[p] = pack2(ex2(alo), ex2(ahi));
        }
        lp0 = l0; lp1 = l1;
    }
    // drain the pipeline
#pragma unroll
    for (int p = 0; p < NPAIR; p++) {
        wsum[p] = add2(wsum[p], evp[p]);
        lx[p]   = fma2(evp[p], lp0, lx[p]);
        ly[p]   = fma2(evp[p], lp1, ly[p]);
    }

    // ---- write partials, layout [plane][ntile][q]: warp-coalesced ----
    const u32 row = ntile * Q_NUM + q0;
#pragma unroll
    for (int p = 0; p < NPAIR; p++) {
        float w0, w1, x0, x1, y0, y1;
        unpack2(wsum[p], w0, w1);
        unpack2(lx[p],   x0, x1);
        unpack2(ly[p],   y0, y1);
        u32 ia = row + (2 * p + 0) * BLOCK;   // consecutive q across warp
        u32 ib = row + (2 * p + 1) * BLOCK;
        g_partial[0u * PLANE + ia] = w0;
        g_partial[1u * PLANE + ia] = x0;
        g_partial[2u * PLANE + ia] = y0;
        g_partial[0u * PLANE + ib] = w1;
        g_partial[1u * PLANE + ib] = x1;
        g_partial[2u * PLANE + ib] = y1;
    }
}

// ---- reduction: 64 parts x 4 q4-groups per block, 256 blocks ------------
// Each thread sums 2-3 tiles (3 planes, independent LDG.128s), then a
// 6-level fixed-order smem tree -> bitwise deterministic. 65K threads.
// (= R9/R10 reduce, best measured)
#define RPARTS 64
__global__ __launch_bounds__(256)
void sknn_reduce_kernel(float* __restrict__ out) {
    __shared__ float4 sred[3][RPARTS][4];   // 12 KB
    const u32 part = threadIdx.x >> 2;            // 0..63
    const u32 g    = threadIdx.x & 3;             // q4-group within block
    const u32 q4   = blockIdx.x * 4 + g;          // global float4 index

    float4 w = make_float4(0.f, 0.f, 0.f, 0.f);
    float4 x = w, y = w;
    const float4* p0 = reinterpret_cast<const float4*>(g_partial + 0u * PLANE);
    const float4* p1 = reinterpret_cast<const float4*>(g_partial + 1u * PLANE);
    const float4* p2 = reinterpret_cast<const float4*>(g_partial + 2u * PLANE);
    for (u32 c = part; c < NTILES; c += RPARTS) {
        const u32 idx = c * (Q_NUM / 4) + q4;
        float4 a = p0[idx], b = p1[idx], d = p2[idx];
        w.x += a.x; w.y += a.y; w.z += a.z; w.w += a.w;
        x.x += b.x; x.y += b.y; x.z += b.z; x.w += b.w;
        y.x += d.x; y.y += d.y; y.z += d.z; y.w += d.w;
    }
    sred[0][part][g] = w; sred[1][part][g] = x; sred[2][part][g] = y;
    __syncthreads();

#pragma unroll
    for (u32 sft = RPARTS / 2; sft >= 1; sft >>= 1) {
        if (part < sft) {
#pragma unroll
            for (int pl = 0; pl < 3; pl++) {
                float4 a = sred[pl][part][g], b = sred[pl][part + sft][g];
                a.x += b.x; a.y += b.y; a.z += b.z; a.w += b.w;
                sred[pl][part][g] = a;
            }
        }
        __syncthreads();
    }

    if (part == 0) {
        float4 wt = sred[0][0][g], xt = sred[1][0][g], yt = sred[2][0][g];
        const u32 qb = q4 * 4;
        out[(qb + 0) * 2 + 0] = xt.x / wt.x;
        out[(qb + 0) * 2 + 1] = yt.x / wt.x;
        out[(qb + 1) * 2 + 0] = xt.y / wt.y;
        out[(qb + 1) * 2 + 1] = yt.y / wt.y;
        out[(qb + 2) * 2 + 0] = xt.z / wt.z;
        out[(qb + 2) * 2 + 1] = yt.z / wt.z;
        out[(qb + 3) * 2 + 0] = xt.w / wt.w;
        out[(qb + 3) * 2 + 1] = yt.w / wt.w;
    }
}

// ---------------- launch -------------------------------------------------
extern "C" void kernel_launch(void* const* d_in, const int* in_sizes, int n_in,
                              void* d_out, int out_size) {
    (void)in_sizes; (void)n_in; (void)out_size;
    const float* rss   = (const float*)d_in[0];  // [4096, 5]
    const float* Radio = (const float*)d_in[1];  // [50000, 5]
    const float* Loc   = (const float*)d_in[2];  // [50000, 2]
    const float* sigma = (const float*)d_in[3];  // [1]
    float* out = (float*)d_out;                  // [4096, 2]

    dim3 grid(QTILES, NTILES);
    sknn_main_kernel<<<grid, BLOCK>>>(rss, Radio, Loc, sigma);

    // 256 blocks x 256 thr: 64 parts x 16 queries (4 float4 groups) each
    sknn_reduce_kernel<<<(Q_NUM / 4) / 4, 256>>>(out);
}